// round 1
// baseline (speedup 1.0000x reference)
#include <cuda_runtime.h>
#include <cuda_bf16.h>

// Problem constants (shapes fixed by the dataset).
#define B   256      // queries
#define D   768      // feature dim (6*128)
#define N   131072   // database rows
#define L   512      // output row length

#define TN  64       // db rows per block
#define KC  16       // k-chunk
#define QS  260      // q smem stride (256 + 4 pad)
#define DS  68       // db smem stride (64 + 4 pad)

// Scratch (no allocations allowed).
__device__ float              g_invn[N];
__device__ unsigned long long g_best[B];

__device__ __forceinline__ unsigned sortable(float v) {
    unsigned u = __float_as_uint(v);
    return (u & 0x80000000u) ? ~u : (u | 0x80000000u);
}

// ---------------- init: reset per-query best ----------------
__global__ void init_kernel() {
    g_best[threadIdx.x] = 0ull;   // sortable-key 0 == smallest possible
}

// ---------------- inverse norms of database rows ----------------
__global__ void invnorm_kernel(const float* __restrict__ db) {
    const int n = blockIdx.x;
    const float* row = db + (size_t)n * D;
    int t = threadIdx.x;               // 256 threads
    float a = row[t], b = row[t + 256], c = row[t + 512];
    float s = a * a + b * b + c * c;
#pragma unroll
    for (int m = 16; m; m >>= 1) s += __shfl_xor_sync(0xffffffffu, s, m);
    __shared__ float ws[8];
    if ((t & 31) == 0) ws[t >> 5] = s;
    __syncthreads();
    if (t < 8) {
        float v = ws[t];
#pragma unroll
        for (int m = 4; m; m >>= 1) v += __shfl_xor_sync(0xffu, v, m);
        if (t == 0) g_invn[n] = 1.0f / fmaxf(sqrtf(v), 1e-8f);
    }
}

// ---------------- main: dot products + scaled argmax ----------------
__global__ __launch_bounds__(256, 2)
void sim_kernel(const float* __restrict__ x, const float* __restrict__ db) {
    __shared__ float q_s[KC][QS];
    __shared__ float d_s[KC][DS];

    const int tid = threadIdx.x;
    const int tx  = tid & 7;     // n-group (8 rows each)
    const int ty  = tid >> 3;    // q-group (8 queries each), 0..31
    const int n0  = blockIdx.x * TN;

    float acc[8][8];
#pragma unroll
    for (int i = 0; i < 8; i++)
#pragma unroll
        for (int j = 0; j < 8; j++) acc[i][j] = 0.0f;

    for (int k0 = 0; k0 < D; k0 += KC) {
        // Load q tile: thread tid owns query row q=tid, 16 contiguous k's.
        {
            const float4* qp = (const float4*)(x + (size_t)tid * D + k0);
            float4 v0 = qp[0], v1 = qp[1], v2 = qp[2], v3 = qp[3];
            q_s[0][tid]  = v0.x; q_s[1][tid]  = v0.y; q_s[2][tid]  = v0.z; q_s[3][tid]  = v0.w;
            q_s[4][tid]  = v1.x; q_s[5][tid]  = v1.y; q_s[6][tid]  = v1.z; q_s[7][tid]  = v1.w;
            q_s[8][tid]  = v2.x; q_s[9][tid]  = v2.y; q_s[10][tid] = v2.z; q_s[11][tid] = v2.w;
            q_s[12][tid] = v3.x; q_s[13][tid] = v3.y; q_s[14][tid] = v3.z; q_s[15][tid] = v3.w;
        }
        // Load db tile: 64 rows x 16 k = 1024 floats; one float4 per thread.
        {
            const int nr = tid >> 2;          // 0..63
            const int kb = (tid & 3) * 4;     // 0,4,8,12
            float4 dv = *(const float4*)(db + (size_t)(n0 + nr) * D + k0 + kb);
            d_s[kb + 0][nr] = dv.x;
            d_s[kb + 1][nr] = dv.y;
            d_s[kb + 2][nr] = dv.z;
            d_s[kb + 3][nr] = dv.w;
        }
        __syncthreads();

#pragma unroll
        for (int k = 0; k < KC; k++) {
            float qf[8], df[8];
            *(float4*)(qf)     = *(const float4*)&q_s[k][ty * 8];
            *(float4*)(qf + 4) = *(const float4*)&q_s[k][ty * 8 + 4];
            *(float4*)(df)     = *(const float4*)&d_s[k][tx * 8];
            *(float4*)(df + 4) = *(const float4*)&d_s[k][tx * 8 + 4];
#pragma unroll
            for (int i = 0; i < 8; i++)
#pragma unroll
                for (int j = 0; j < 8; j++)
                    acc[i][j] = fmaf(qf[i], df[j], acc[i][j]);
        }
        __syncthreads();
    }

    // Epilogue: scale by db inverse norm, per-query max, packed atomicMax.
    float inv[8];
#pragma unroll
    for (int j = 0; j < 8; j++) inv[j] = g_invn[n0 + tx * 8 + j];

#pragma unroll
    for (int i = 0; i < 8; i++) {
        unsigned long long p = 0ull;
#pragma unroll
        for (int j = 0; j < 8; j++) {
            float v = acc[i][j] * inv[j];
            unsigned nidx = (unsigned)(n0 + tx * 8 + j);
            unsigned long long cand =
                ((unsigned long long)sortable(v) << 32) | (unsigned)(~nidx);
            p = (cand > p) ? cand : p;
        }
        // reduce across the 8 tx lanes (consecutive lanes in warp)
#pragma unroll
        for (int m = 4; m; m >>= 1) {
            unsigned long long o = __shfl_xor_sync(0xffffffffu, p, m);
            p = (o > p) ? o : p;
        }
        if (tx == 0) atomicMax(&g_best[ty * 8 + i], p);
    }
}

// ---------------- gather output rows ----------------
__global__ void gather_kernel(const float* __restrict__ y, float* __restrict__ out) {
    const int b = blockIdx.x;
    unsigned long long p = g_best[b];
    unsigned idx = ~((unsigned)(p & 0xffffffffull));
    const float4* src = (const float4*)(y + (size_t)idx * L);
    float4* dst = (float4*)(out + (size_t)b * L);
    dst[threadIdx.x] = src[threadIdx.x];   // 128 threads x float4 = 512 floats
}

extern "C" void kernel_launch(void* const* d_in, const int* in_sizes, int n_in,
                              void* d_out, int out_size) {
    const float* imu = (const float*)d_in[0];   // [256,6,128] contiguous == [256,768]
    const float* dbx = (const float*)d_in[1];   // [131072,768]
    const float* dby = (const float*)d_in[2];   // [131072,512]
    float* out = (float*)d_out;                 // [256,512]

    init_kernel<<<1, B>>>();
    invnorm_kernel<<<N, 256>>>(dbx);
    sim_kernel<<<N / TN, 256>>>(imu, dbx);
    gather_kernel<<<B, L / 4>>>(dby, out);
}

// round 3
// speedup vs baseline: 6.2106x; 6.2106x over previous
#include <cuda_runtime.h>
#include <cuda_bf16.h>
#include <cstdint>

#define Bq 256      // queries
#define Dk 768      // feature dim
#define Nn 131072   // database rows
#define Lo 512      // output row length

// ---------------- arch feature detection ----------------
#if defined(__CUDA_ARCH_FEAT_SM103_ALL) || defined(__CUDA_ARCH_FEAT_SM100_ALL) || \
    (defined(__CUDA_ARCH_SPECIFIC__) && (__CUDA_ARCH_SPECIFIC__ >= 1000)) ||      \
    (defined(__CUDA_ARCH_FAMILY_SPECIFIC__) && (__CUDA_ARCH_FAMILY_SPECIFIC__ >= 1000))
#define USE_TCGEN05 1
#else
#define USE_TCGEN05 0
#endif

// Shared smem budget for both paths (host requests one size).
#define SMEM_TOTAL 198656

__device__ __nv_bfloat16 g_qh[Bq * Dk];
__device__ __nv_bfloat16 g_ql[Bq * Dk];
__device__ unsigned long long g_best[Bq];

// ---------------- common helpers ----------------
__device__ __forceinline__ uint32_t smem_u32(const void* p) {
    uint32_t a;
    asm("{ .reg .u64 t; cvta.to.shared.u64 t, %1; cvt.u32.u64 %0, t; }"
        : "=r"(a) : "l"(p));
    return a;
}
__device__ __forceinline__ unsigned long long pack_key(float v, unsigned idx) {
    unsigned u = __float_as_uint(v);
    u = (u & 0x80000000u) ? ~u : (u | 0x80000000u);
    return ((unsigned long long)u << 32) | (unsigned)(~idx);
}

// ---------------- init ----------------
__global__ void init_kernel() { g_best[threadIdx.x] = 0ull; }

// ---------------- query split precompute ----------------
__global__ void convert_q_kernel(const float* __restrict__ x) {
    int i = blockIdx.x * 256 + threadIdx.x;
    float f = x[i];
    __nv_bfloat16 h = __float2bfloat16(f);
    float r = f - __bfloat162float(h);
    g_qh[i] = h;
    g_ql[i] = __float2bfloat16(r);
}

#if USE_TCGEN05
// ============================================================================
// tcgen05 path (compiled only in the sm_103a / family-specific pass)
// ============================================================================
#define TILE_N 256
#define TILE_M 128
#define KC 64
#define NCHUNK 12

#define SM_TMEM   0
#define SM_MBAR0  8
#define SM_MBAR1  16
#define SM_INVN   32
#define SM_BUF    2048
#define BUF_QH    0
#define BUF_QL    16384
#define BUF_DH    32768
#define BUF_DL    65536
#define BUF_SIZE  98304

#define IDESC 0x8400490u   // dtype=F32, a/b=BF16, N=256, M=128

__device__ __forceinline__ uint32_t elect1() {
    uint32_t p;
    asm volatile("{ .reg .pred p; elect.sync _|p, 0xFFFFFFFF; selp.b32 %0,1,0,p; }"
                 : "=r"(p));
    return p;
}
#define MBAR_INIT(a, cnt) \
    asm volatile("mbarrier.init.shared.b64 [%0], %1;" :: "r"(a), "r"(cnt) : "memory")
#define MBAR_INVAL(a) \
    asm volatile("mbarrier.inval.shared.b64 [%0];" :: "r"(a) : "memory")
#define MBAR_WAIT(a, par) do {                                                   \
    uint32_t _m = (a), _p = (par), _d;                                           \
    asm volatile("{ .reg .pred p; mbarrier.try_wait.parity.acquire.cta.shared::cta.b64 p, [%1], %2; selp.b32 %0,1,0,p; }" \
        : "=r"(_d) : "r"(_m), "r"(_p) : "memory");                               \
    if (!_d) {                                                                   \
        asm volatile("{ .reg .pred P1; WL%=:"                                    \
            " mbarrier.try_wait.parity.acquire.cta.shared::cta.b64 P1, [%0], %1, 0x989680;" \
            " @P1 bra.uni WD%=; bra.uni WL%=; WD%=: }"                           \
            :: "r"(_m), "r"(_p) : "memory");                                     \
    }                                                                            \
} while (0)

#define TM_ALLOC(sa, n) \
    asm volatile("tcgen05.alloc.cta_group::1.sync.aligned.shared::cta.b32 [%0], %1;" :: "r"(sa), "r"(n) : "memory")
#define TM_RELINQ() \
    asm volatile("tcgen05.relinquish_alloc_permit.cta_group::1.sync.aligned;")
#define TM_DEALLOC(t, n) \
    asm volatile("tcgen05.dealloc.cta_group::1.sync.aligned.b32 %0, %1;" :: "r"(t), "r"(n))
#define TM_COMMIT(mb) \
    asm volatile("tcgen05.commit.cta_group::1.mbarrier::arrive::one.shared::cluster.b64 [%0];" :: "r"(mb) : "memory")
#define TM_FENCE_AFTER()  asm volatile("tcgen05.fence::after_thread_sync;" ::: "memory")
#define TM_FENCE_BEFORE() asm volatile("tcgen05.fence::before_thread_sync;" ::: "memory")
#define TM_WAIT_LD()      asm volatile("tcgen05.wait::ld.sync.aligned;" ::: "memory")

#define LDTM_X32(r, addr) \
    asm volatile( \
        "tcgen05.ld.sync.aligned.32x32b.x32.b32 " \
        "{%0,%1,%2,%3,%4,%5,%6,%7,%8,%9,%10,%11,%12,%13,%14,%15," \
        "%16,%17,%18,%19,%20,%21,%22,%23,%24,%25,%26,%27,%28,%29,%30,%31}, [%32];" \
        : "=r"((r)[0]),"=r"((r)[1]),"=r"((r)[2]),"=r"((r)[3]), \
          "=r"((r)[4]),"=r"((r)[5]),"=r"((r)[6]),"=r"((r)[7]), \
          "=r"((r)[8]),"=r"((r)[9]),"=r"((r)[10]),"=r"((r)[11]), \
          "=r"((r)[12]),"=r"((r)[13]),"=r"((r)[14]),"=r"((r)[15]), \
          "=r"((r)[16]),"=r"((r)[17]),"=r"((r)[18]),"=r"((r)[19]), \
          "=r"((r)[20]),"=r"((r)[21]),"=r"((r)[22]),"=r"((r)[23]), \
          "=r"((r)[24]),"=r"((r)[25]),"=r"((r)[26]),"=r"((r)[27]), \
          "=r"((r)[28]),"=r"((r)[29]),"=r"((r)[30]),"=r"((r)[31]) \
        : "r"(addr))

__device__ __forceinline__ uint64_t mk_desc(uint32_t addr) {
    const uint64_t BASE = (2ULL << 61) | (1ULL << 46) | (64ULL << 32) | (1ULL << 16);
    return BASE | (uint64_t)((addr >> 4) & 0x3FFF);
}
__device__ __forceinline__ void mma_ss(uint32_t d, uint64_t a, uint64_t b, uint32_t en) {
    asm volatile(
        "{\n\t.reg .pred p;\n\tsetp.ne.u32 p, %3, 0;\n\t"
        "tcgen05.mma.cta_group::1.kind::f16 [%0], %1, %2, %4, {%5,%5,%5,%5}, p;\n\t}"
        :: "r"(d), "l"(a), "l"(b), "r"(en), "r"(IDESC), "r"(0u) : "memory");
}
__device__ __forceinline__ uint32_t b2u(__nv_bfloat162 h) {
    return *reinterpret_cast<uint32_t*>(&h);
}

__global__ void __launch_bounds__(256, 1) sim_kernel(const float* __restrict__ db) {
    extern __shared__ char smem[];
    const uint32_t sb = smem_u32(smem);
    const int tid = threadIdx.x;
    const int wid = tid >> 5;
    const int dbtile = blockIdx.x >> 1;
    const int q0 = (blockIdx.x & 1) * TILE_M;
    const int n0 = dbtile * TILE_N;

    if (tid == 0) { MBAR_INIT(sb + SM_MBAR0, 1); MBAR_INIT(sb + SM_MBAR1, 1); }
    if (wid == 0) { TM_ALLOC(sb + SM_TMEM, 256); TM_RELINQ(); }
    __syncthreads();
    uint32_t tmem;
    asm volatile("ld.shared.b32 %0,[%1];" : "=r"(tmem) : "r"(sb + SM_TMEM));

    float ps[16];
#pragma unroll
    for (int v = 0; v < 16; v++) ps[v] = 0.f;
    const int g  = tid >> 4;
    const int cs = tid & 15;

#pragma unroll 1
    for (int c = 0; c < NCHUNK; c++) {
        const int bufo = SM_BUF + (c & 1) * BUF_SIZE;
        char* buf = smem + bufo;
        if (c >= 2) {
            MBAR_WAIT(sb + ((c & 1) ? SM_MBAR1 : SM_MBAR0), ((c >> 1) - 1) & 1);
        }
        const int k0 = c * KC;

#pragma unroll
        for (int v = 0; v < 8; v++) {
            const __nv_bfloat16* src = (v < 4) ? g_qh : g_ql;
            int ii  = (tid + 256 * v) & 1023;
            int row = ii >> 3, c16 = ii & 7;
            uint4 val = *(const uint4*)(src + (size_t)(q0 + row) * Dk + k0 + c16 * 8);
            uint32_t off = (uint32_t)(row * 128 + c16 * 16);
            uint32_t sw  = off ^ ((off >> 3) & 0x70);
            *(uint4*)(buf + ((v < 4) ? BUF_QH : BUF_QL) + sw) = val;
        }
        {
            const float* dbase = db + (size_t)n0 * Dk + k0;
#pragma unroll
            for (int v = 0; v < 16; v++) {
                int row = g + 16 * v;
                float4 f = *(const float4*)(dbase + (size_t)row * Dk + cs * 4);
                ps[v] = fmaf(f.x, f.x, fmaf(f.y, f.y, fmaf(f.z, f.z, fmaf(f.w, f.w, ps[v]))));
                __nv_bfloat162 h01 = __floats2bfloat162_rn(f.x, f.y);
                __nv_bfloat162 h23 = __floats2bfloat162_rn(f.z, f.w);
                __nv_bfloat162 l01 = __floats2bfloat162_rn(f.x - __low2float(h01),
                                                           f.y - __high2float(h01));
                __nv_bfloat162 l23 = __floats2bfloat162_rn(f.z - __low2float(h23),
                                                           f.w - __high2float(h23));
                uint32_t off = (uint32_t)(row * 128 + cs * 8);
                uint32_t sw  = off ^ ((off >> 3) & 0x70);
                *(uint2*)(buf + BUF_DH + sw) = make_uint2(b2u(h01), b2u(h23));
                *(uint2*)(buf + BUF_DL + sw) = make_uint2(b2u(l01), b2u(l23));
            }
        }
        asm volatile("fence.proxy.async.shared::cta;" ::: "memory");
        __syncthreads();

        if (wid == 0 && elect1()) {
            const uint32_t sbuf = sb + bufo;
            uint64_t aH = mk_desc(sbuf + BUF_QH), aL = mk_desc(sbuf + BUF_QL);
            uint64_t bH = mk_desc(sbuf + BUF_DH), bL = mk_desc(sbuf + BUF_DL);
#pragma unroll
            for (int k = 0; k < 4; k++) mma_ss(tmem, aH + 2 * k, bH + 2 * k, (c | k) != 0);
#pragma unroll
            for (int k = 0; k < 4; k++) mma_ss(tmem, aH + 2 * k, bL + 2 * k, 1u);
#pragma unroll
            for (int k = 0; k < 4; k++) mma_ss(tmem, aL + 2 * k, bH + 2 * k, 1u);
            TM_COMMIT(sb + ((c & 1) ? SM_MBAR1 : SM_MBAR0));
        }
    }

    float* s_invn = (float*)(smem + SM_INVN);
#pragma unroll
    for (int v = 0; v < 16; v++) {
        float s = ps[v];
        s += __shfl_xor_sync(0xffffffffu, s, 1);
        s += __shfl_xor_sync(0xffffffffu, s, 2);
        s += __shfl_xor_sync(0xffffffffu, s, 4);
        s += __shfl_xor_sync(0xffffffffu, s, 8);
        if (cs == 0) s_invn[g + 16 * v] = 1.0f / fmaxf(sqrtf(s), 1e-8f);
    }

    MBAR_WAIT(sb + SM_MBAR0, 1);
    MBAR_WAIT(sb + SM_MBAR1, 1);
    TM_FENCE_AFTER();
    __syncthreads();

    const int lane = tid & 31;
    const int q    = q0 + (wid & 3) * 32 + lane;
    const int cb   = (wid >> 2) * 128;
    unsigned long long best = 0ull;
#pragma unroll
    for (int i = 0; i < 4; i++) {
        uint32_t r[32];
        LDTM_X32(r, tmem + cb + 32 * i);
        TM_WAIT_LD();
#pragma unroll
        for (int j = 0; j < 32; j++) {
            int col = cb + 32 * i + j;
            float v = __uint_as_float(r[j]) * s_invn[col];
            unsigned long long cand = pack_key(v, (unsigned)(n0 + col));
            best = (cand > best) ? cand : best;
        }
    }
    TM_FENCE_BEFORE();
    atomicMax(&g_best[q], best);

    __syncthreads();
    if (tid == 0) { MBAR_INVAL(sb + SM_MBAR0); MBAR_INVAL(sb + SM_MBAR1); }
    if (wid == 0) { TM_DEALLOC(tmem, 256); }
}

#else
// ============================================================================
// Fallback path: mma.sync.m16n8k16 bf16x3 (baseline ISA, assembles on sm_103)
// ============================================================================
#define F_KS   72            // smem k-stride (elements) -> 144B rows, ldsm conflict-free
#define F_QH   0
#define F_QL   18432
#define F_DH   36864
#define F_DL   55296
#define F_BUF  73728
#define F_INVN 147456

__device__ __forceinline__ void ldsm_x4(uint32_t* r, uint32_t a) {
    asm volatile("ldmatrix.sync.aligned.m8n8.x4.shared.b16 {%0,%1,%2,%3}, [%4];"
                 : "=r"(r[0]), "=r"(r[1]), "=r"(r[2]), "=r"(r[3]) : "r"(a));
}
__device__ __forceinline__ void mma16816(float* d, const uint32_t* a, const uint32_t* b) {
    asm volatile(
        "mma.sync.aligned.m16n8k16.row.col.f32.bf16.bf16.f32 "
        "{%0,%1,%2,%3},{%4,%5,%6,%7},{%8,%9},{%0,%1,%2,%3};"
        : "+f"(d[0]), "+f"(d[1]), "+f"(d[2]), "+f"(d[3])
        : "r"(a[0]), "r"(a[1]), "r"(a[2]), "r"(a[3]), "r"(b[0]), "r"(b[1]));
}

__global__ void __launch_bounds__(256, 1) sim_kernel(const float* __restrict__ db) {
    extern __shared__ char smem[];
    const uint32_t sb32 = smem_u32(smem);
    const int tid  = threadIdx.x;
    const int lane = tid & 31;
    const int w    = tid >> 5;
    const int q0   = (blockIdx.x & 1) * 128;
    const int n0   = (blockIdx.x >> 1) * 256;
    const int qb   = (w & 3) * 32;          // local query block (32 q)
    const int nb   = (w >> 2) * 64;         // local db block (64 n)
    float* s_invn  = (float*)(smem + F_INVN);

    unsigned long long best[2][2] = {{0ull, 0ull}, {0ull, 0ull}};

#pragma unroll 1
    for (int nh = 0; nh < 2; nh++) {
        const int nbase = n0 + nh * 128;
        float acc[2][8][4];
#pragma unroll
        for (int a = 0; a < 2; a++)
#pragma unroll
            for (int b = 0; b < 8; b++)
#pragma unroll
                for (int r = 0; r < 4; r++) acc[a][b][r] = 0.f;
        float ps = 0.f;
        const int row  = tid >> 1;
        const int half = tid & 1;

#pragma unroll 1
        for (int c = 0; c < 12; c++) {
            const int bufo = (c & 1) * F_BUF;
            const int k0 = c * 64;
            // ---- load q chunk (bf16 hi/lo) ----
            {
                const uint4* qh = (const uint4*)(g_qh + (size_t)(q0 + row) * Dk + k0 + half * 32);
                const uint4* ql = (const uint4*)(g_ql + (size_t)(q0 + row) * Dk + k0 + half * 32);
                char* dh = smem + bufo + F_QH + row * 144 + half * 64;
                char* dl = smem + bufo + F_QL + row * 144 + half * 64;
#pragma unroll
                for (int i = 0; i < 4; i++) {
                    ((uint4*)dh)[i] = qh[i];
                    ((uint4*)dl)[i] = ql[i];
                }
            }
            // ---- load db chunk fp32 -> hi/lo bf16, accumulate norms ----
            {
                const float4* dsrc = (const float4*)(db + (size_t)(nbase + row) * Dk + k0 + half * 32);
                char* ph = smem + bufo + F_DH + row * 144 + half * 64;
                char* pl = smem + bufo + F_DL + row * 144 + half * 64;
#pragma unroll
                for (int i = 0; i < 8; i++) {
                    float4 f = dsrc[i];
                    ps = fmaf(f.x, f.x, fmaf(f.y, f.y, fmaf(f.z, f.z, fmaf(f.w, f.w, ps))));
                    __nv_bfloat162 h01 = __floats2bfloat162_rn(f.x, f.y);
                    __nv_bfloat162 h23 = __floats2bfloat162_rn(f.z, f.w);
                    __nv_bfloat162 l01 = __floats2bfloat162_rn(f.x - __low2float(h01),
                                                               f.y - __high2float(h01));
                    __nv_bfloat162 l23 = __floats2bfloat162_rn(f.z - __low2float(h23),
                                                               f.w - __high2float(h23));
                    *(uint2*)(ph + i * 8) =
                        make_uint2(*(uint32_t*)&h01, *(uint32_t*)&h23);
                    *(uint2*)(pl + i * 8) =
                        make_uint2(*(uint32_t*)&l01, *(uint32_t*)&l23);
                }
            }
            __syncthreads();

            const uint32_t sqh = sb32 + bufo + F_QH;
            const uint32_t sql = sb32 + bufo + F_QL;
            const uint32_t sdh = sb32 + bufo + F_DH;
            const uint32_t sdl = sb32 + bufo + F_DL;
#pragma unroll
            for (int ks = 0; ks < 4; ks++) {
                uint32_t aH[2][4], aL[2][4];
#pragma unroll
                for (int mi = 0; mi < 2; mi++) {
                    uint32_t ao = (uint32_t)((qb + mi * 16 + (lane & 15)) * 144 +
                                             ks * 32 + (lane >> 4) * 16);
                    ldsm_x4(aH[mi], sqh + ao);
                    ldsm_x4(aL[mi], sql + ao);
                }
#pragma unroll
                for (int nip = 0; nip < 4; nip++) {
                    uint32_t bo = (uint32_t)((nb + nip * 16 + (lane & 7) +
                                              ((lane >> 4) & 1) * 8) * 144 +
                                             ks * 32 + ((lane >> 3) & 1) * 16);
                    uint32_t bh[4], bl[4];
                    ldsm_x4(bh, sdh + bo);
                    ldsm_x4(bl, sdl + bo);
#pragma unroll
                    for (int mi = 0; mi < 2; mi++)
#pragma unroll
                        for (int s = 0; s < 2; s++) {
                            float* d = acc[mi][nip * 2 + s];
                            mma16816(d, aH[mi], &bh[2 * s]);
                            mma16816(d, aL[mi], &bh[2 * s]);
                            mma16816(d, aH[mi], &bl[2 * s]);
                        }
                }
            }
        }
        // ---- inverse norms for this n-half ----
        {
            float s = ps + __shfl_xor_sync(0xffffffffu, ps, 1);
            if (!(tid & 1)) s_invn[row] = 1.0f / fmaxf(sqrtf(s), 1e-8f);
        }
        __syncthreads();
        // ---- fold into per-(q)-best ----
#pragma unroll
        for (int mi = 0; mi < 2; mi++)
#pragma unroll
            for (int g8 = 0; g8 < 2; g8++) {
                unsigned long long b = best[mi][g8];
#pragma unroll
                for (int ni = 0; ni < 8; ni++)
#pragma unroll
                    for (int s = 0; s < 2; s++) {
                        int nl = nb + ni * 8 + (lane & 3) * 2 + s;
                        float v = acc[mi][ni][g8 * 2 + s] * s_invn[nl];
                        unsigned long long cand =
                            pack_key(v, (unsigned)(nbase + nl));
                        b = (cand > b) ? cand : b;
                    }
                best[mi][g8] = b;
            }
        __syncthreads();
    }

    // reduce over the 4 lanes sharing each q row, then atomic
#pragma unroll
    for (int mi = 0; mi < 2; mi++)
#pragma unroll
        for (int g8 = 0; g8 < 2; g8++) {
            unsigned long long b = best[mi][g8];
            unsigned long long o;
            o = __shfl_xor_sync(0xffffffffu, b, 1); b = (o > b) ? o : b;
            o = __shfl_xor_sync(0xffffffffu, b, 2); b = (o > b) ? o : b;
            if ((lane & 3) == 0) {
                int q = q0 + qb + mi * 16 + g8 * 8 + (lane >> 2);
                atomicMax(&g_best[q], b);
            }
        }
}
#endif  // USE_TCGEN05

// ---------------- gather ----------------
__global__ void gather_kernel(const float* __restrict__ y, float* __restrict__ out) {
    const int b = blockIdx.x;
    unsigned long long p = g_best[b];
    unsigned idx = ~((unsigned)(p & 0xffffffffull));
    const float4* src = (const float4*)(y + (size_t)idx * Lo);
    float4* dst = (float4*)(out + (size_t)b * Lo);
    dst[threadIdx.x] = src[threadIdx.x];
}

extern "C" void kernel_launch(void* const* d_in, const int* in_sizes, int n_in,
                              void* d_out, int out_size) {
    const float* imu = (const float*)d_in[0];
    const float* dbx = (const float*)d_in[1];
    const float* dby = (const float*)d_in[2];
    float* out = (float*)d_out;

    cudaFuncSetAttribute(sim_kernel, cudaFuncAttributeMaxDynamicSharedMemorySize,
                         SMEM_TOTAL);

    init_kernel<<<1, Bq>>>();
    convert_q_kernel<<<Dk, 256>>>(imu);
    sim_kernel<<<1024, 256, SMEM_TOTAL>>>(dbx);
    gather_kernel<<<Bq, Lo / 4>>>(dby, out);
}